// round 13
// baseline (speedup 1.0000x reference)
#include <cuda_runtime.h>

#define NTHREADS 256
#define D_MODEL  2048
#define BATCH    8192
#define LUT_N    4096
#define GRID     1024

// (sin, cos) interleaved lookup with linear interpolation over [0, 2*pi).
// Matches reference lut_sin_cos to ~interp-error precision.
__device__ __forceinline__ float2 lut_lookup(float theta, const float2* __restrict__ sc) {
    const float INV2PI = 0.15915494309189535f;
    float u = theta * INV2PI;
    u = u - floorf(u);                  // in [0, 1)
    float pos = u * (float)LUT_N;       // in [0, 4096] (can hit 4096.0 by rounding)
    int i0 = (int)pos;
    i0 = min(i0, LUT_N - 1);
    float frac = pos - (float)i0;
    float2 a = sc[i0];
    float2 b = sc[i0 + 1];
    return make_float2(fmaf(frac, b.x - a.x, a.x),   // sin
                       fmaf(frac, b.y - a.y, a.y));  // cos
}

__global__ void __launch_bounds__(NTHREADS, 3)
liquid_echo_kernel(const float* __restrict__ x_real,
                   const float* __restrict__ x_imag,
                   const float* __restrict__ t,
                   const float* __restrict__ mem_real,
                   const float* __restrict__ mem_imag,
                   const float* __restrict__ w_trigger,
                   const float* __restrict__ b_trigger,
                   const float* __restrict__ w_state,
                   const float* __restrict__ b_state,
                   const float* __restrict__ kptr,
                   const float* __restrict__ sin_table,
                   const float* __restrict__ cos_table,
                   float* __restrict__ out)
{
    __shared__ float2 sc[LUT_N + 1];          // 32776 B
    __shared__ float  red[NTHREADS / 32];

    const int tid = threadIdx.x;

    // Build interleaved (sin, cos) table once per block.
    for (int i = tid; i < LUT_N; i += NTHREADS)
        sc[i] = make_float2(sin_table[i], cos_table[i]);
    if (tid == 0)
        sc[LUT_N] = make_float2(sin_table[0], cos_table[0]);

    // Per-column parameters for this thread's 8 columns (row-invariant).
    const int cbase = tid * 8;
    float invwl_t[8], bt2[8], invwl_s[8], bs2[8];
#pragma unroll
    for (int j = 0; j < 8; j++) {
        int c = cbase + j;
        invwl_t[j] = 1.0f / (1.0f + fabsf(__ldg(w_trigger + c)));
        bt2[j]     = 2.0f * __ldg(b_trigger + c);
        invwl_s[j] = 1.0f / (1.0f + fabsf(__ldg(w_state + c)));
        bs2[j]     = 2.0f * __ldg(b_state + c);
    }
    const float k_eff     = fabsf(__ldg(kptr)) + 0.1f;
    const float inv_scale = 0.02209708691207961f;   // 1/sqrt(2048)
    const float PHI       = 1.6180339887498949f;
    const size_t IM_OFF   = (size_t)BATCH * D_MODEL;

    __syncthreads();

    for (int row = blockIdx.x; row < BATCH; row += GRID) {
        const float  tphi2 = 2.0f * __ldg(t + row) * PHI;
        const size_t off   = (size_t)row * D_MODEL + cbase;

        // Load x and memory (float4 vectorized, 8 contiguous columns).
        float4 xr0 = *(const float4*)(x_real + off);
        float4 xr1 = *(const float4*)(x_real + off + 4);
        float4 xi0 = *(const float4*)(x_imag + off);
        float4 xi1 = *(const float4*)(x_imag + off + 4);
        float4 mr0 = *(const float4*)(mem_real + off);
        float4 mr1 = *(const float4*)(mem_real + off + 4);
        float4 mi0 = *(const float4*)(mem_imag + off);
        float4 mi1 = *(const float4*)(mem_imag + off + 4);

        float xr[8] = {xr0.x, xr0.y, xr0.z, xr0.w, xr1.x, xr1.y, xr1.z, xr1.w};
        float xi[8] = {xi0.x, xi0.y, xi0.z, xi0.w, xi1.x, xi1.y, xi1.z, xi1.w};
        float mr[8] = {mr0.x, mr0.y, mr0.z, mr0.w, mr1.x, mr1.y, mr1.z, mr1.w};
        float mi[8] = {mi0.x, mi0.y, mi0.z, mi0.w, mi1.x, mi1.y, mi1.z, mi1.w};

        // Phase 1: trigger phase via cos(a+b)/sin(a+b) identity, accumulate
        // interference = sum(cos(theta_sum)*x_r + sin(theta_sum)*x_i).
        float xs[8], ms[8];
        float acc = 0.0f;
#pragma unroll
        for (int j = 0; j < 8; j++) {
            xs[j] = xr[j] + xi[j];
            ms[j] = mr[j] + mi[j];
            float theta = fmaf(xs[j], invwl_t[j], bt2[j] + tphi2);
            float2 scv  = lut_lookup(theta, sc);
            acc = fmaf(scv.y, xr[j], acc);   // cos * x_real
            acc = fmaf(scv.x, xi[j], acc);   // sin * x_imag
        }

        // Block reduction of interference.
        float v = acc;
#pragma unroll
        for (int o = 16; o > 0; o >>= 1)
            v += __shfl_xor_sync(0xffffffffu, v, o);
        if ((tid & 31) == 0) red[tid >> 5] = v;
        __syncthreads();
        float total = red[0] + red[1] + red[2] + red[3]
                    + red[4] + red[5] + red[6] + red[7];
        __syncthreads();   // protect red[] before next row's writes

        float inter = total * inv_scale;
        inter = fminf(1.0f, fmaxf(-1.0f, inter));
        float x_inv = 0.5f * (1.0f - inter);
        float alpha = __expf(-k_eff * x_inv);

        // Phase 2: blend (only the sum is needed for the combined angle),
        // re-evolve, outputs are cos/sin of the combined state angle.
        float er[8], ei[8];
#pragma unroll
        for (int j = 0; j < 8; j++) {
            // blended_sum = alpha*xs + (1-alpha)*ms = ms + alpha*(xs - ms)
            float bsum   = fmaf(alpha, xs[j] - ms[j], ms[j]);
            float theta2 = fmaf(bsum, invwl_s[j], bs2[j] + tphi2);
            float2 scv2  = lut_lookup(theta2, sc);
            er[j] = scv2.y;   // cos -> evolved_real
            ei[j] = scv2.x;   // sin -> evolved_imag
        }

        *(float4*)(out + off)              = make_float4(er[0], er[1], er[2], er[3]);
        *(float4*)(out + off + 4)          = make_float4(er[4], er[5], er[6], er[7]);
        *(float4*)(out + IM_OFF + off)     = make_float4(ei[0], ei[1], ei[2], ei[3]);
        *(float4*)(out + IM_OFF + off + 4) = make_float4(ei[4], ei[5], ei[6], ei[7]);
    }
}

extern "C" void kernel_launch(void* const* d_in, const int* in_sizes, int n_in,
                              void* d_out, int out_size) {
    const float* x_real    = (const float*)d_in[0];
    const float* x_imag    = (const float*)d_in[1];
    const float* t         = (const float*)d_in[2];
    const float* mem_real  = (const float*)d_in[3];
    const float* mem_imag  = (const float*)d_in[4];
    const float* w_trigger = (const float*)d_in[5];
    const float* b_trigger = (const float*)d_in[6];
    const float* w_state   = (const float*)d_in[7];
    const float* b_state   = (const float*)d_in[8];
    const float* k         = (const float*)d_in[9];
    const float* sin_table = (const float*)d_in[10];
    const float* cos_table = (const float*)d_in[11];
    float* out = (float*)d_out;

    liquid_echo_kernel<<<GRID, NTHREADS>>>(
        x_real, x_imag, t, mem_real, mem_imag,
        w_trigger, b_trigger, w_state, b_state, k,
        sin_table, cos_table, out);
}

// round 14
// speedup vs baseline: 1.0072x; 1.0072x over previous
#include <cuda_runtime.h>

#define NTHREADS 256
#define D_MODEL  2048
#define BATCH    8192
#define LUT_N    4096
#define GRID     1024

// (sin, cos) interleaved lookup with linear interpolation over [0, 2*pi).
// Matches reference lut_sin_cos to ~interp-error precision.
__device__ __forceinline__ float2 lut_lookup(float theta, const float2* __restrict__ sc) {
    const float INV2PI = 0.15915494309189535f;
    float u = theta * INV2PI;
    u = u - floorf(u);                  // in [0, 1)
    float pos = u * (float)LUT_N;       // in [0, 4096] (can hit 4096.0 by rounding)
    int i0 = (int)pos;
    i0 = min(i0, LUT_N - 1);
    float frac = pos - (float)i0;
    float2 a = sc[i0];
    float2 b = sc[i0 + 1];
    return make_float2(fmaf(frac, b.x - a.x, a.x),   // sin
                       fmaf(frac, b.y - a.y, a.y));  // cos
}

__global__ void __launch_bounds__(NTHREADS, 3)
liquid_echo_kernel(const float* __restrict__ x_real,
                   const float* __restrict__ x_imag,
                   const float* __restrict__ t,
                   const float* __restrict__ mem_real,
                   const float* __restrict__ mem_imag,
                   const float* __restrict__ w_trigger,
                   const float* __restrict__ b_trigger,
                   const float* __restrict__ w_state,
                   const float* __restrict__ b_state,
                   const float* __restrict__ kptr,
                   const float* __restrict__ sin_table,
                   const float* __restrict__ cos_table,
                   float* __restrict__ out)
{
    __shared__ float2 sc[LUT_N + 1];          // 32776 B
    __shared__ float  red[NTHREADS / 32];

    const int tid = threadIdx.x;

    // Build interleaved (sin, cos) table once per block.
    for (int i = tid; i < LUT_N; i += NTHREADS)
        sc[i] = make_float2(sin_table[i], cos_table[i]);
    if (tid == 0)
        sc[LUT_N] = make_float2(sin_table[0], cos_table[0]);

    // Per-column parameters for this thread's 8 columns (row-invariant).
    const int cbase = tid * 8;
    float invwl_t[8], bt2[8], invwl_s[8], bs2[8];
#pragma unroll
    for (int j = 0; j < 8; j++) {
        int c = cbase + j;
        invwl_t[j] = 1.0f / (1.0f + fabsf(__ldg(w_trigger + c)));
        bt2[j]     = 2.0f * __ldg(b_trigger + c);
        invwl_s[j] = 1.0f / (1.0f + fabsf(__ldg(w_state + c)));
        bs2[j]     = 2.0f * __ldg(b_state + c);
    }
    const float k_eff     = fabsf(__ldg(kptr)) + 0.1f;
    const float inv_scale = 0.02209708691207961f;   // 1/sqrt(2048)
    const float PHI       = 1.6180339887498949f;
    const size_t IM_OFF   = (size_t)BATCH * D_MODEL;

    __syncthreads();

    for (int row = blockIdx.x; row < BATCH; row += GRID) {
        const float  tphi2 = 2.0f * __ldg(t + row) * PHI;
        const size_t off   = (size_t)row * D_MODEL + cbase;

        // Load x and memory (float4 vectorized, 8 contiguous columns).
        float4 xr0 = *(const float4*)(x_real + off);
        float4 xr1 = *(const float4*)(x_real + off + 4);
        float4 xi0 = *(const float4*)(x_imag + off);
        float4 xi1 = *(const float4*)(x_imag + off + 4);
        float4 mr0 = *(const float4*)(mem_real + off);
        float4 mr1 = *(const float4*)(mem_real + off + 4);
        float4 mi0 = *(const float4*)(mem_imag + off);
        float4 mi1 = *(const float4*)(mem_imag + off + 4);

        float xr[8] = {xr0.x, xr0.y, xr0.z, xr0.w, xr1.x, xr1.y, xr1.z, xr1.w};
        float xi[8] = {xi0.x, xi0.y, xi0.z, xi0.w, xi1.x, xi1.y, xi1.z, xi1.w};
        float mr[8] = {mr0.x, mr0.y, mr0.z, mr0.w, mr1.x, mr1.y, mr1.z, mr1.w};
        float mi[8] = {mi0.x, mi0.y, mi0.z, mi0.w, mi1.x, mi1.y, mi1.z, mi1.w};

        // Phase 1: trigger phase via cos(a+b)/sin(a+b) identity, accumulate
        // interference = sum(cos(theta_sum)*x_r + sin(theta_sum)*x_i).
        float xs[8], ms[8];
        float acc = 0.0f;
#pragma unroll
        for (int j = 0; j < 8; j++) {
            xs[j] = xr[j] + xi[j];
            ms[j] = mr[j] + mi[j];
            float theta = fmaf(xs[j], invwl_t[j], bt2[j] + tphi2);
            float2 scv  = lut_lookup(theta, sc);
            acc = fmaf(scv.y, xr[j], acc);   // cos * x_real
            acc = fmaf(scv.x, xi[j], acc);   // sin * x_imag
        }

        // Block reduction of interference.
        float v = acc;
#pragma unroll
        for (int o = 16; o > 0; o >>= 1)
            v += __shfl_xor_sync(0xffffffffu, v, o);
        if ((tid & 31) == 0) red[tid >> 5] = v;
        __syncthreads();
        float total = red[0] + red[1] + red[2] + red[3]
                    + red[4] + red[5] + red[6] + red[7];
        __syncthreads();   // protect red[] before next row's writes

        float inter = total * inv_scale;
        inter = fminf(1.0f, fmaxf(-1.0f, inter));
        float x_inv = 0.5f * (1.0f - inter);
        float alpha = __expf(-k_eff * x_inv);

        // Phase 2: blend (only the sum is needed for the combined angle),
        // re-evolve, outputs are cos/sin of the combined state angle.
        float er[8], ei[8];
#pragma unroll
        for (int j = 0; j < 8; j++) {
            // blended_sum = alpha*xs + (1-alpha)*ms = ms + alpha*(xs - ms)
            float bsum   = fmaf(alpha, xs[j] - ms[j], ms[j]);
            float theta2 = fmaf(bsum, invwl_s[j], bs2[j] + tphi2);
            float2 scv2  = lut_lookup(theta2, sc);
            er[j] = scv2.y;   // cos -> evolved_real
            ei[j] = scv2.x;   // sin -> evolved_imag
        }

        *(float4*)(out + off)              = make_float4(er[0], er[1], er[2], er[3]);
        *(float4*)(out + off + 4)          = make_float4(er[4], er[5], er[6], er[7]);
        *(float4*)(out + IM_OFF + off)     = make_float4(ei[0], ei[1], ei[2], ei[3]);
        *(float4*)(out + IM_OFF + off + 4) = make_float4(ei[4], ei[5], ei[6], ei[7]);
    }
}

extern "C" void kernel_launch(void* const* d_in, const int* in_sizes, int n_in,
                              void* d_out, int out_size) {
    const float* x_real    = (const float*)d_in[0];
    const float* x_imag    = (const float*)d_in[1];
    const float* t         = (const float*)d_in[2];
    const float* mem_real  = (const float*)d_in[3];
    const float* mem_imag  = (const float*)d_in[4];
    const float* w_trigger = (const float*)d_in[5];
    const float* b_trigger = (const float*)d_in[6];
    const float* w_state   = (const float*)d_in[7];
    const float* b_state   = (const float*)d_in[8];
    const float* k         = (const float*)d_in[9];
    const float* sin_table = (const float*)d_in[10];
    const float* cos_table = (const float*)d_in[11];
    float* out = (float*)d_out;

    liquid_echo_kernel<<<GRID, NTHREADS>>>(
        x_real, x_imag, t, mem_real, mem_imag,
        w_trigger, b_trigger, w_state, b_state, k,
        sin_table, cos_table, out);
}

// round 15
// speedup vs baseline: 1.0110x; 1.0037x over previous
#include <cuda_runtime.h>

#define NTHREADS 256
#define D_MODEL  2048
#define BATCH    8192
#define LUT_N    4096
#define GRID     1024

// (sin, cos) interleaved lookup with linear interpolation over [0, 2*pi).
// Matches reference lut_sin_cos to ~interp-error precision.
__device__ __forceinline__ float2 lut_lookup(float theta, const float2* __restrict__ sc) {
    const float INV2PI = 0.15915494309189535f;
    float u = theta * INV2PI;
    u = u - floorf(u);                  // in [0, 1)
    float pos = u * (float)LUT_N;       // in [0, 4096] (can hit 4096.0 by rounding)
    int i0 = (int)pos;
    i0 = min(i0, LUT_N - 1);
    float frac = pos - (float)i0;
    float2 a = sc[i0];
    float2 b = sc[i0 + 1];
    return make_float2(fmaf(frac, b.x - a.x, a.x),   // sin
                       fmaf(frac, b.y - a.y, a.y));  // cos
}

__global__ void __launch_bounds__(NTHREADS, 3)
liquid_echo_kernel(const float* __restrict__ x_real,
                   const float* __restrict__ x_imag,
                   const float* __restrict__ t,
                   const float* __restrict__ mem_real,
                   const float* __restrict__ mem_imag,
                   const float* __restrict__ w_trigger,
                   const float* __restrict__ b_trigger,
                   const float* __restrict__ w_state,
                   const float* __restrict__ b_state,
                   const float* __restrict__ kptr,
                   const float* __restrict__ sin_table,
                   const float* __restrict__ cos_table,
                   float* __restrict__ out)
{
    __shared__ float2 sc[LUT_N + 1];          // 32776 B
    __shared__ float  red[NTHREADS / 32];

    const int tid = threadIdx.x;

    // Build interleaved (sin, cos) table once per block.
    for (int i = tid; i < LUT_N; i += NTHREADS)
        sc[i] = make_float2(sin_table[i], cos_table[i]);
    if (tid == 0)
        sc[LUT_N] = make_float2(sin_table[0], cos_table[0]);

    // Per-column parameters for this thread's 8 columns (row-invariant).
    const int cbase = tid * 8;
    float invwl_t[8], bt2[8], invwl_s[8], bs2[8];
#pragma unroll
    for (int j = 0; j < 8; j++) {
        int c = cbase + j;
        invwl_t[j] = 1.0f / (1.0f + fabsf(__ldg(w_trigger + c)));
        bt2[j]     = 2.0f * __ldg(b_trigger + c);
        invwl_s[j] = 1.0f / (1.0f + fabsf(__ldg(w_state + c)));
        bs2[j]     = 2.0f * __ldg(b_state + c);
    }
    const float k_eff     = fabsf(__ldg(kptr)) + 0.1f;
    const float inv_scale = 0.02209708691207961f;   // 1/sqrt(2048)
    const float PHI       = 1.6180339887498949f;
    const size_t IM_OFF   = (size_t)BATCH * D_MODEL;

    __syncthreads();

    for (int row = blockIdx.x; row < BATCH; row += GRID) {
        const float  tphi2 = 2.0f * __ldg(t + row) * PHI;
        const size_t off   = (size_t)row * D_MODEL + cbase;

        // Load x and memory (float4 vectorized, 8 contiguous columns).
        float4 xr0 = *(const float4*)(x_real + off);
        float4 xr1 = *(const float4*)(x_real + off + 4);
        float4 xi0 = *(const float4*)(x_imag + off);
        float4 xi1 = *(const float4*)(x_imag + off + 4);
        float4 mr0 = *(const float4*)(mem_real + off);
        float4 mr1 = *(const float4*)(mem_real + off + 4);
        float4 mi0 = *(const float4*)(mem_imag + off);
        float4 mi1 = *(const float4*)(mem_imag + off + 4);

        float xr[8] = {xr0.x, xr0.y, xr0.z, xr0.w, xr1.x, xr1.y, xr1.z, xr1.w};
        float xi[8] = {xi0.x, xi0.y, xi0.z, xi0.w, xi1.x, xi1.y, xi1.z, xi1.w};
        float mr[8] = {mr0.x, mr0.y, mr0.z, mr0.w, mr1.x, mr1.y, mr1.z, mr1.w};
        float mi[8] = {mi0.x, mi0.y, mi0.z, mi0.w, mi1.x, mi1.y, mi1.z, mi1.w};

        // Phase 1: trigger phase via cos(a+b)/sin(a+b) identity, accumulate
        // interference = sum(cos(theta_sum)*x_r + sin(theta_sum)*x_i).
        float xs[8], ms[8];
        float acc = 0.0f;
#pragma unroll
        for (int j = 0; j < 8; j++) {
            xs[j] = xr[j] + xi[j];
            ms[j] = mr[j] + mi[j];
            float theta = fmaf(xs[j], invwl_t[j], bt2[j] + tphi2);
            float2 scv  = lut_lookup(theta, sc);
            acc = fmaf(scv.y, xr[j], acc);   // cos * x_real
            acc = fmaf(scv.x, xi[j], acc);   // sin * x_imag
        }

        // Block reduction of interference.
        float v = acc;
#pragma unroll
        for (int o = 16; o > 0; o >>= 1)
            v += __shfl_xor_sync(0xffffffffu, v, o);
        if ((tid & 31) == 0) red[tid >> 5] = v;
        __syncthreads();
        float total = red[0] + red[1] + red[2] + red[3]
                    + red[4] + red[5] + red[6] + red[7];
        __syncthreads();   // protect red[] before next row's writes

        float inter = total * inv_scale;
        inter = fminf(1.0f, fmaxf(-1.0f, inter));
        float x_inv = 0.5f * (1.0f - inter);
        float alpha = __expf(-k_eff * x_inv);

        // Phase 2: blend (only the sum is needed for the combined angle),
        // re-evolve, outputs are cos/sin of the combined state angle.
        float er[8], ei[8];
#pragma unroll
        for (int j = 0; j < 8; j++) {
            // blended_sum = alpha*xs + (1-alpha)*ms = ms + alpha*(xs - ms)
            float bsum   = fmaf(alpha, xs[j] - ms[j], ms[j]);
            float theta2 = fmaf(bsum, invwl_s[j], bs2[j] + tphi2);
            float2 scv2  = lut_lookup(theta2, sc);
            er[j] = scv2.y;   // cos -> evolved_real
            ei[j] = scv2.x;   // sin -> evolved_imag
        }

        *(float4*)(out + off)              = make_float4(er[0], er[1], er[2], er[3]);
        *(float4*)(out + off + 4)          = make_float4(er[4], er[5], er[6], er[7]);
        *(float4*)(out + IM_OFF + off)     = make_float4(ei[0], ei[1], ei[2], ei[3]);
        *(float4*)(out + IM_OFF + off + 4) = make_float4(ei[4], ei[5], ei[6], ei[7]);
    }
}

extern "C" void kernel_launch(void* const* d_in, const int* in_sizes, int n_in,
                              void* d_out, int out_size) {
    const float* x_real    = (const float*)d_in[0];
    const float* x_imag    = (const float*)d_in[1];
    const float* t         = (const float*)d_in[2];
    const float* mem_real  = (const float*)d_in[3];
    const float* mem_imag  = (const float*)d_in[4];
    const float* w_trigger = (const float*)d_in[5];
    const float* b_trigger = (const float*)d_in[6];
    const float* w_state   = (const float*)d_in[7];
    const float* b_state   = (const float*)d_in[8];
    const float* k         = (const float*)d_in[9];
    const float* sin_table = (const float*)d_in[10];
    const float* cos_table = (const float*)d_in[11];
    float* out = (float*)d_out;

    liquid_echo_kernel<<<GRID, NTHREADS>>>(
        x_real, x_imag, t, mem_real, mem_imag,
        w_trigger, b_trigger, w_state, b_state, k,
        sin_table, cos_table, out);
}